// round 6
// baseline (speedup 1.0000x reference)
#include <cuda_runtime.h>
#include <cuda_fp16.h>
#include <cstdint>

#define EMBD   1024
#define HEADS  16
#define HD     64
#define BATCH  4
#define SEQ    2048
#define MROWS  (BATCH*SEQ)   // 8192

// ---------------- scratch (allocation-free: __device__ globals) ----------------
__device__ __align__(128) __half g_xh  [MROWS*EMBD];        // x in fp16
__device__ __align__(128) __half g_wqt [EMBD*EMBD];         // Wq^T [N][K]
__device__ __align__(128) __half g_wkvt[2*HD*EMBD];         // [Wk^T ; Wv^T] [128][1024]
__device__ __align__(128) __half g_wot [EMBD*EMBD];         // Wo^T
__device__ __align__(128) float  g_bkv [2*HD];              // [bk ; bv]
__device__ __align__(128) __half g_q   [BATCH*HEADS*SEQ*HD];// Q [B,H,S,Dh]
__device__ __align__(128) __half g_k   [BATCH*SEQ*HD];      // K [B,S,Dh]
__device__ __align__(128) __half g_vt  [BATCH*HD*SEQ];      // V^T [B,Dh,S]
__device__ __align__(128) __half g_ao  [MROWS*EMBD];        // attn out fp16

// ---------------- helpers ----------------
__device__ __forceinline__ unsigned h2_as_u32(__half2 h) {
    return *reinterpret_cast<unsigned*>(&h);
}

__device__ __forceinline__ uint32_t sptr(const void* p) {
    return (uint32_t)__cvta_generic_to_shared(p);
}

__device__ __forceinline__ void ldsm4(unsigned r[4], uint32_t a) {
    asm volatile("ldmatrix.sync.aligned.m8n8.x4.shared.b16 {%0,%1,%2,%3}, [%4];"
                 : "=r"(r[0]), "=r"(r[1]), "=r"(r[2]), "=r"(r[3]) : "r"(a));
}

// ---------------- mma.sync m16n8k16 fp16 -> fp32 ----------------
__device__ __forceinline__ void mma16816(float c[4], const unsigned a[4], const unsigned b[2]) {
    asm volatile(
        "mma.sync.aligned.m16n8k16.row.col.f32.f16.f16.f32 "
        "{%0,%1,%2,%3}, {%4,%5,%6,%7}, {%8,%9}, {%0,%1,%2,%3};\n"
        : "+f"(c[0]), "+f"(c[1]), "+f"(c[2]), "+f"(c[3])
        : "r"(a[0]), "r"(a[1]), "r"(a[2]), "r"(a[3]), "r"(b[0]), "r"(b[1]));
}

// ---------------- fp32 -> fp16 convert ----------------
__global__ void f2h_kernel(const float* __restrict__ in, __half* __restrict__ out, int n4) {
    int i = blockIdx.x * blockDim.x + threadIdx.x;
    if (i < n4) {
        float4 v = ((const float4*)in)[i];
        __half2* o = (__half2*)out + (size_t)i * 2;
        o[0] = __floats2half2_rn(v.x, v.y);
        o[1] = __floats2half2_rn(v.z, v.w);
    }
}

// ---------------- fp32 [R][C] -> fp16 [C][R] transpose-convert ----------------
__global__ void tconv_kernel(const float* __restrict__ in, __half* __restrict__ out, int R, int C) {
    __shared__ float t[32][33];
    const int c0 = blockIdx.x * 32, r0 = blockIdx.y * 32;
    const int tx = threadIdx.x, ty = threadIdx.y;
#pragma unroll
    for (int j = 0; j < 32; j += 8)
        t[ty + j][tx] = in[(size_t)(r0 + ty + j) * C + c0 + tx];
    __syncthreads();
#pragma unroll
    for (int j = 0; j < 32; j += 8)
        out[(size_t)(c0 + ty + j) * R + r0 + tx] = __float2half(t[tx][ty + j]);
}

__global__ void bcat_kernel(const float* __restrict__ a, const float* __restrict__ b,
                            float* __restrict__ o) {
    int i = threadIdx.x;
    o[i] = (i < HD) ? a[i] : b[i - HD];
}

// ---------------- HGEMM: C = A[M,1024] @ Bt[N,1024]^T + bias ----------------
// 128x128 tile, 256 thr, ldmatrix fragment loads.
// EPI: 0 = fp32 row-major; 2 = fp16 remap [B,H,S,Dh]; 4 = fused KV split
template<int EPI>
__global__ __launch_bounds__(256)
void hgemm_kernel(const __half* __restrict__ A, const __half* __restrict__ Bt,
                  const float* __restrict__ bias, void* __restrict__ Cout, int N)
{
    constexpr int BM = 128, BN = 128, BK = 32, K = 1024;
    constexpr int WM = 64;       // 2x4 warps -> warp tile 64x32
    constexpr int MF = 4, NF = 4;

    __shared__ __half As[BM][40];
    __shared__ __half Bs[BN][40];

    const int tid  = threadIdx.x;
    const int bm   = blockIdx.y * BM, bn = blockIdx.x * BN;
    const int warp = tid >> 5, lane = tid & 31;
    const int wm   = warp >> 2, wn = warp & 3;
    const int g    = lane >> 2, t2 = (lane & 3) * 2;
    const int lr   = tid >> 2, lc = (tid & 3) * 8;

    // ldmatrix lane->address components
    const int arow  = lane & 15;
    const int acol8 = (lane >> 4) << 3;
    const int brow  = ((lane >> 4) << 3) + (lane & 7);
    const int bcol8 = ((lane >> 3) & 1) << 3;

    float acc[MF][NF][4];
#pragma unroll
    for (int i = 0; i < MF; i++)
#pragma unroll
        for (int j = 0; j < NF; j++)
#pragma unroll
            for (int q = 0; q < 4; q++) acc[i][j][q] = 0.f;

    const int nk = K / BK;
    uint4 ra0, ra1, rb0, rb1;
    ra0 = *(const uint4*)&A[(size_t)(bm + lr) * K + lc];
    ra1 = *(const uint4*)&A[(size_t)(bm + lr + 64) * K + lc];
    rb0 = *(const uint4*)&Bt[(size_t)(bn + lr) * K + lc];
    rb1 = *(const uint4*)&Bt[(size_t)(bn + lr + 64) * K + lc];

    for (int kt = 0; kt < nk; kt++) {
        *(uint4*)&As[lr][lc]      = ra0;
        *(uint4*)&As[lr + 64][lc] = ra1;
        *(uint4*)&Bs[lr][lc]      = rb0;
        *(uint4*)&Bs[lr + 64][lc] = rb1;
        __syncthreads();

        if (kt + 1 < nk) {
            const int ko = (kt + 1) * BK + lc;
            ra0 = *(const uint4*)&A[(size_t)(bm + lr) * K + ko];
            ra1 = *(const uint4*)&A[(size_t)(bm + lr + 64) * K + ko];
            rb0 = *(const uint4*)&Bt[(size_t)(bn + lr) * K + ko];
            rb1 = *(const uint4*)&Bt[(size_t)(bn + lr + 64) * K + ko];
        }

#pragma unroll
        for (int ks = 0; ks < BK; ks += 16) {
            unsigned af[MF][4], bf[NF][2];
#pragma unroll
            for (int mf = 0; mf < MF; mf++)
                ldsm4(af[mf], sptr(&As[wm * WM + mf * 16 + arow][ks + acol8]));
#pragma unroll
            for (int np = 0; np < NF / 2; np++) {
                unsigned t[4];
                ldsm4(t, sptr(&Bs[wn * 32 + np * 16 + brow][ks + bcol8]));
                bf[2*np][0]   = t[0]; bf[2*np][1]   = t[1];
                bf[2*np+1][0] = t[2]; bf[2*np+1][1] = t[3];
            }
#pragma unroll
            for (int mf = 0; mf < MF; mf++)
#pragma unroll
                for (int nf = 0; nf < NF; nf++)
                    mma16816(acc[mf][nf], af[mf], bf[nf]);
        }
        __syncthreads();
    }

#pragma unroll
    for (int mf = 0; mf < MF; mf++) {
#pragma unroll
        for (int nf = 0; nf < NF; nf++) {
            const int m = bm + wm * WM + mf * 16 + g;
            const int n = bn + wn * 32 + nf * 8 + t2;
            const float b0 = bias[n], b1 = bias[n + 1];
            const float v00 = acc[mf][nf][0] + b0, v01 = acc[mf][nf][1] + b1;
            const float v10 = acc[mf][nf][2] + b0, v11 = acc[mf][nf][3] + b1;
            if (EPI == 0) {
                float* C = (float*)Cout;
                *(float2*)&C[(size_t)m * N + n]       = make_float2(v00, v01);
                *(float2*)&C[(size_t)(m + 8) * N + n] = make_float2(v10, v11);
            } else if (EPI == 2) {
                __half* C = (__half*)Cout;
                const int h = n >> 6, d = n & 63;
                const int b_ = m >> 11, s = m & (SEQ - 1);
                *(__half2*)&C[(((size_t)(b_ * HEADS + h) * SEQ) + s) * HD + d] =
                    __floats2half2_rn(v00, v01);
                *(__half2*)&C[(((size_t)(b_ * HEADS + h) * SEQ) + s + 8) * HD + d] =
                    __floats2half2_rn(v10, v11);
            } else { // EPI == 4, fused KV
                const int b_ = m >> 11, s = m & (SEQ - 1);
                if (n < HD) {
                    __half* C = (__half*)Cout;
                    *(__half2*)&C[((size_t)(b_ * SEQ) + s) * HD + n]     = __floats2half2_rn(v00, v01);
                    *(__half2*)&C[((size_t)(b_ * SEQ) + s + 8) * HD + n] = __floats2half2_rn(v10, v11);
                } else {
                    const int d = n - HD;
                    g_vt[((size_t)(b_ * HD) + d)     * SEQ + s]     = __float2half(v00);
                    g_vt[((size_t)(b_ * HD) + d + 1) * SEQ + s]     = __float2half(v01);
                    g_vt[((size_t)(b_ * HD) + d)     * SEQ + s + 8] = __float2half(v10);
                    g_vt[((size_t)(b_ * HD) + d + 1) * SEQ + s + 8] = __float2half(v11);
                }
            }
        }
    }
}

// ---------------- flash attention, registers-only S/P + ldmatrix ----------------
// grid (SEQ/128, B*H), 256 thr (8 warps x 16 rows). Q[B,H,S,Dh], K[B,S,Dh], Vt[B,Dh,S]
__global__ __launch_bounds__(256)
void attn_kernel(const __half* __restrict__ Q, const __half* __restrict__ Kg,
                 const __half* __restrict__ Vt, __half* __restrict__ O)
{
    __shared__ __half Qs[128][72];
    __shared__ __half Ks[64][72];
    __shared__ __half Vs[64][72];

    const int tid  = threadIdx.x;
    const int bh   = blockIdx.y, b = bh >> 4, h = bh & 15, qt = blockIdx.x;
    const int warp = tid >> 5, lane = tid & 31;
    const int g    = lane >> 2, t2 = (lane & 3) * 2;

    // ldmatrix B-operand lane->address components
    const int brow  = ((lane >> 4) << 3) + (lane & 7);
    const int bcol8 = ((lane >> 3) & 1) << 3;

    {
        const __half* Qb = Q + ((size_t)bh * SEQ + qt * 128) * HD;
        const int lr = tid >> 1, lc = (tid & 1) * 32;
#pragma unroll
        for (int u = 0; u < 4; u++)
            *(uint4*)&Qs[lr][lc + u * 8] = *(const uint4*)&Qb[lr * HD + lc + u * 8];
    }
    __syncthreads();
    unsigned qf[4][4];
    {
        const int arow  = lane & 15;
        const int acol8 = (lane >> 4) << 3;
#pragma unroll
        for (int kb = 0; kb < 4; kb++)
            ldsm4(qf[kb], sptr(&Qs[warp * 16 + arow][kb * 16 + acol8]));
    }

    float oacc[8][4];
#pragma unroll
    for (int nf = 0; nf < 8; nf++)
#pragma unroll
        for (int q = 0; q < 4; q++) oacc[nf][q] = 0.f;
    float m0 = -1e30f, m1 = -1e30f, l0 = 0.f, l1 = 0.f;
    const float scl = 0.125f;

    const __half* Kb = Kg + (size_t)b * SEQ * HD;
    const __half* Vb = Vt + (size_t)b * HD * SEQ;

    const int r0c = tid >> 3,         cu0 = (tid & 7) * 8;
    const int r1c = (tid + 256) >> 3, cu1 = ((tid + 256) & 7) * 8;

    uint4 kr0, kr1, vr0, vr1;
    kr0 = *(const uint4*)&Kb[(size_t)r0c * HD + cu0];
    kr1 = *(const uint4*)&Kb[(size_t)r1c * HD + cu1];
    vr0 = *(const uint4*)&Vb[(size_t)r0c * SEQ + cu0];
    vr1 = *(const uint4*)&Vb[(size_t)r1c * SEQ + cu1];

    for (int kt = 0; kt < SEQ / 64; kt++) {
        if (kt) __syncthreads();
        *(uint4*)&Ks[r0c][cu0] = kr0;
        *(uint4*)&Ks[r1c][cu1] = kr1;
        *(uint4*)&Vs[r0c][cu0] = vr0;
        *(uint4*)&Vs[r1c][cu1] = vr1;
        __syncthreads();

        if (kt + 1 < SEQ / 64) {
            const int kvo = (kt + 1) * 64;
            kr0 = *(const uint4*)&Kb[((size_t)kvo + r0c) * HD + cu0];
            kr1 = *(const uint4*)&Kb[((size_t)kvo + r1c) * HD + cu1];
            vr0 = *(const uint4*)&Vb[(size_t)r0c * SEQ + kvo + cu0];
            vr1 = *(const uint4*)&Vb[(size_t)r1c * SEQ + kvo + cu1];
        }

        // S = Q @ K^T
        float sacc[8][4];
#pragma unroll
        for (int nf = 0; nf < 8; nf++)
#pragma unroll
            for (int q = 0; q < 4; q++) sacc[nf][q] = 0.f;
#pragma unroll
        for (int kb = 0; kb < 4; kb++) {
            unsigned kf[4][4];
#pragma unroll
            for (int np = 0; np < 4; np++)
                ldsm4(kf[np], sptr(&Ks[np * 16 + brow][kb * 16 + bcol8]));
#pragma unroll
            for (int nf = 0; nf < 8; nf++) {
                const unsigned bfr[2] = { kf[nf >> 1][(nf & 1) * 2],
                                          kf[nf >> 1][(nf & 1) * 2 + 1] };
                mma16816(sacc[nf], qf[kb], bfr);
            }
        }

        // online softmax in registers
        float mx0 = -1e30f, mx1 = -1e30f;
#pragma unroll
        for (int nf = 0; nf < 8; nf++) {
#pragma unroll
            for (int q = 0; q < 4; q++) sacc[nf][q] *= scl;
            mx0 = fmaxf(mx0, fmaxf(sacc[nf][0], sacc[nf][1]));
            mx1 = fmaxf(mx1, fmaxf(sacc[nf][2], sacc[nf][3]));
        }
        mx0 = fmaxf(mx0, __shfl_xor_sync(0xffffffffu, mx0, 1));
        mx0 = fmaxf(mx0, __shfl_xor_sync(0xffffffffu, mx0, 2));
        mx1 = fmaxf(mx1, __shfl_xor_sync(0xffffffffu, mx1, 1));
        mx1 = fmaxf(mx1, __shfl_xor_sync(0xffffffffu, mx1, 2));
        const float mn0 = fmaxf(m0, mx0), mn1 = fmaxf(m1, mx1);

        unsigned ph[8][2];
        float ps0 = 0.f, ps1 = 0.f;
#pragma unroll
        for (int nf = 0; nf < 8; nf++) {
            const float p00 = __expf(sacc[nf][0] - mn0);
            const float p01 = __expf(sacc[nf][1] - mn0);
            const float p10 = __expf(sacc[nf][2] - mn1);
            const float p11 = __expf(sacc[nf][3] - mn1);
            ps0 += p00 + p01;
            ps1 += p10 + p11;
            ph[nf][0] = h2_as_u32(__floats2half2_rn(p00, p01));
            ph[nf][1] = h2_as_u32(__floats2half2_rn(p10, p11));
        }
        ps0 += __shfl_xor_sync(0xffffffffu, ps0, 1);
        ps0 += __shfl_xor_sync(0xffffffffu, ps0, 2);
        ps1 += __shfl_xor_sync(0xffffffffu, ps1, 1);
        ps1 += __shfl_xor_sync(0xffffffffu, ps1, 2);
        const float rs0 = __expf(m0 - mn0), rs1 = __expf(m1 - mn1);
        l0 = l0 * rs0 + ps0;  m0 = mn0;
        l1 = l1 * rs1 + ps1;  m1 = mn1;
#pragma unroll
        for (int nf = 0; nf < 8; nf++) {
            oacc[nf][0] *= rs0; oacc[nf][1] *= rs0;
            oacc[nf][2] *= rs1; oacc[nf][3] *= rs1;
        }

        // O += P @ V
#pragma unroll
        for (int kb = 0; kb < 4; kb++) {
            const unsigned af[4] = { ph[2*kb][0], ph[2*kb][1], ph[2*kb+1][0], ph[2*kb+1][1] };
            unsigned vf[4][4];
#pragma unroll
            for (int np = 0; np < 4; np++)
                ldsm4(vf[np], sptr(&Vs[np * 16 + brow][kb * 16 + bcol8]));
#pragma unroll
            for (int nd = 0; nd < 8; nd++) {
                const unsigned bfr[2] = { vf[nd >> 1][(nd & 1) * 2],
                                          vf[nd >> 1][(nd & 1) * 2 + 1] };
                mma16816(oacc[nd], af, bfr);
            }
        }
    }

    const float i0 = 1.f / l0, i1 = 1.f / l1;
    const int row = warp * 16 + g;
    const int s0 = qt * 128 + row;
#pragma unroll
    for (int nf = 0; nf < 8; nf++) {
        const int d = h * HD + nf * 8 + t2;
        *(__half2*)&O[((size_t)(b * SEQ) + s0) * EMBD + d] =
            __floats2half2_rn(oacc[nf][0] * i0, oacc[nf][1] * i0);
        *(__half2*)&O[((size_t)(b * SEQ) + s0 + 8) * EMBD + d] =
            __floats2half2_rn(oacc[nf][2] * i1, oacc[nf][3] * i1);
    }
}

// ---------------- launch ----------------
extern "C" void kernel_launch(void* const* d_in, const int* in_sizes, int n_in,
                              void* d_out, int out_size)
{
    const float* x  = (const float*)d_in[0];
    const float* Wq = (const float*)d_in[1];
    const float* bq = (const float*)d_in[2];
    const float* Wk = (const float*)d_in[3];
    const float* bk = (const float*)d_in[4];
    const float* Wv = (const float*)d_in[5];
    const float* bv = (const float*)d_in[6];
    const float* Wo = (const float*)d_in[7];
    const float* bo = (const float*)d_in[8];
    float* out = (float*)d_out;

    __half *xh, *wqt, *wkvt, *wot, *q, *k, *vt, *ao;
    float *bkv;
    cudaGetSymbolAddress((void**)&xh,   g_xh);
    cudaGetSymbolAddress((void**)&wqt,  g_wqt);
    cudaGetSymbolAddress((void**)&wkvt, g_wkvt);
    cudaGetSymbolAddress((void**)&wot,  g_wot);
    cudaGetSymbolAddress((void**)&bkv,  g_bkv);
    cudaGetSymbolAddress((void**)&q,    g_q);
    cudaGetSymbolAddress((void**)&k,    g_k);
    cudaGetSymbolAddress((void**)&vt,   g_vt);
    cudaGetSymbolAddress((void**)&ao,   g_ao);

    // fp16 conversions / weight transposes
    f2h_kernel<<<(MROWS * EMBD / 4 + 255) / 256, 256>>>(x, xh, MROWS * EMBD / 4);
    tconv_kernel<<<dim3(EMBD / 32, EMBD / 32), dim3(32, 8)>>>(Wq, wqt, EMBD, EMBD);
    tconv_kernel<<<dim3(HD   / 32, EMBD / 32), dim3(32, 8)>>>(Wk, wkvt, EMBD, HD);
    tconv_kernel<<<dim3(HD   / 32, EMBD / 32), dim3(32, 8)>>>(Wv, wkvt + (size_t)HD * EMBD, EMBD, HD);
    tconv_kernel<<<dim3(EMBD / 32, EMBD / 32), dim3(32, 8)>>>(Wo, wot, EMBD, EMBD);
    bcat_kernel<<<1, 2 * HD>>>(bk, bv, bkv);

    // projections
    hgemm_kernel<2><<<dim3(EMBD / 128, MROWS / 128), 256>>>(xh, wqt, bq, q, EMBD);
    hgemm_kernel<4><<<dim3(1,          MROWS / 128), 256>>>(xh, wkvt, bkv, k, 2 * HD);

    // flash attention
    attn_kernel<<<dim3(SEQ / 128, BATCH * HEADS), 256>>>(q, k, vt, ao);

    // output projection -> fp32 d_out
    hgemm_kernel<0><<<dim3(EMBD / 128, MROWS / 128), 256>>>(ao, wot, bo, out, EMBD);
}

// round 7
// speedup vs baseline: 1.2247x; 1.2247x over previous
#include <cuda_runtime.h>
#include <cuda_fp16.h>
#include <cstdint>

#define EMBD   1024
#define HEADS  16
#define HD     64
#define BATCH  4
#define SEQ    2048
#define MROWS  (BATCH*SEQ)   // 8192
#define NQKV   (EMBD + 2*HD) // 1152

// ---------------- scratch (allocation-free: __device__ globals) ----------------
__device__ __align__(128) __half g_xh   [MROWS*EMBD];        // x in fp16
__device__ __align__(128) __half g_wqkvt[NQKV*EMBD];         // [Wq^T;Wk^T;Wv^T] [1152][1024]
__device__ __align__(128) __half g_wot  [EMBD*EMBD];         // Wo^T
__device__ __align__(128) float  g_bqkv [NQKV];              // [bq;bk;bv]
__device__ __align__(128) __half g_q    [BATCH*HEADS*SEQ*HD];// Q [B,H,S,Dh]
__device__ __align__(128) __half g_k    [BATCH*SEQ*HD];      // K [B,S,Dh]
__device__ __align__(128) __half g_vt   [BATCH*HD*SEQ];      // V^T [B,Dh,S]
__device__ __align__(128) __half g_ao   [MROWS*EMBD];        // attn out fp16

// ---------------- helpers ----------------
__device__ __forceinline__ unsigned h2_as_u32(__half2 h) {
    return *reinterpret_cast<unsigned*>(&h);
}
__device__ __forceinline__ uint32_t sptr(const void* p) {
    return (uint32_t)__cvta_generic_to_shared(p);
}
__device__ __forceinline__ void ldsm4(unsigned r[4], uint32_t a) {
    asm volatile("ldmatrix.sync.aligned.m8n8.x4.shared.b16 {%0,%1,%2,%3}, [%4];"
                 : "=r"(r[0]), "=r"(r[1]), "=r"(r[2]), "=r"(r[3]) : "r"(a));
}
__device__ __forceinline__ void cpa16(uint32_t dst, const void* src) {
    asm volatile("cp.async.ca.shared.global [%0], [%1], 16;" :: "r"(dst), "l"(src));
}
#define CP_COMMIT() asm volatile("cp.async.commit_group;" ::: "memory")
#define CP_WAIT(n)  asm volatile("cp.async.wait_group %0;" :: "n"(n) : "memory")

// ---------------- mma.sync m16n8k16 fp16 -> fp32 ----------------
__device__ __forceinline__ void mma16816(float c[4], const unsigned a[4], const unsigned b[2]) {
    asm volatile(
        "mma.sync.aligned.m16n8k16.row.col.f32.f16.f16.f32 "
        "{%0,%1,%2,%3}, {%4,%5,%6,%7}, {%8,%9}, {%0,%1,%2,%3};\n"
        : "+f"(c[0]), "+f"(c[1]), "+f"(c[2]), "+f"(c[3])
        : "r"(a[0]), "r"(a[1]), "r"(a[2]), "r"(a[3]), "r"(b[0]), "r"(b[1]));
}

// ---------------- small prep kernels ----------------
__global__ void f2h_kernel(const float* __restrict__ in, __half* __restrict__ out, int n4) {
    int i = blockIdx.x * blockDim.x + threadIdx.x;
    if (i < n4) {
        float4 v = ((const float4*)in)[i];
        __half2* o = (__half2*)out + (size_t)i * 2;
        o[0] = __floats2half2_rn(v.x, v.y);
        o[1] = __floats2half2_rn(v.z, v.w);
    }
}

__global__ void tconv_kernel(const float* __restrict__ in, __half* __restrict__ out, int R, int C) {
    __shared__ float t[32][33];
    const int c0 = blockIdx.x * 32, r0 = blockIdx.y * 32;
    const int tx = threadIdx.x, ty = threadIdx.y;
#pragma unroll
    for (int j = 0; j < 32; j += 8)
        t[ty + j][tx] = in[(size_t)(r0 + ty + j) * C + c0 + tx];
    __syncthreads();
#pragma unroll
    for (int j = 0; j < 32; j += 8)
        out[(size_t)(c0 + ty + j) * R + r0 + tx] = __float2half(t[tx][ty + j]);
}

// Wk and Wv transposed into g_wqkvt rows [1024..1088) and [1088..1152)
__global__ void tconv2_kernel(const float* __restrict__ wk, const float* __restrict__ wv,
                              __half* __restrict__ outbase) {
    __shared__ float t[32][33];
    const float* in = blockIdx.z ? wv : wk;
    __half* out = outbase + (size_t)(blockIdx.z ? (EMBD + HD) : EMBD) * EMBD;
    const int c0 = blockIdx.x * 32, r0 = blockIdx.y * 32;
    const int tx = threadIdx.x, ty = threadIdx.y;
#pragma unroll
    for (int j = 0; j < 32; j += 8)
        t[ty + j][tx] = in[(size_t)(r0 + ty + j) * HD + c0 + tx];
    __syncthreads();
#pragma unroll
    for (int j = 0; j < 32; j += 8)
        out[(size_t)(c0 + ty + j) * EMBD + r0 + tx] = __float2half(t[tx][ty + j]);
}

__global__ void bqkv_kernel(const float* __restrict__ bq, const float* __restrict__ bk,
                            const float* __restrict__ bv, float* __restrict__ o) {
    int i = blockIdx.x * 256 + threadIdx.x;
    if (i < EMBD) o[i] = bq[i];
    else if (i < EMBD + HD) o[i] = bk[i - EMBD];
    else if (i < NQKV) o[i] = bv[i - EMBD - HD];
}

// ---------------- HGEMM with 4-stage cp.async: C = A[M,1024] @ Bt[N,1024]^T + bias ----
// EPI: 0 = fp32 row-major (O proj); 5 = fused QKV split
#define GEMM_STAGES 4
#define GEMM_SMEM   (GEMM_STAGES * 2 * 128 * 40 * 2)   // 81920 B

template<int EPI>
__global__ __launch_bounds__(256)
void hgemm_kernel(const __half* __restrict__ A, const __half* __restrict__ Bt,
                  const float* __restrict__ bias, void* __restrict__ Cout, int N)
{
    constexpr int BK = 32, K = 1024, NT = K / BK;     // 32 k-tiles
    constexpr int STG_B = 2 * 128 * 40 * 2;           // bytes per stage (A+B)
    extern __shared__ __half sm[];
    const uint32_t sbase = sptr(sm);

    const int tid  = threadIdx.x;
    const int bm   = blockIdx.y * 128, bn = blockIdx.x * 128;
    const int warp = tid >> 5, lane = tid & 31;
    const int wm   = warp >> 2, wn = warp & 3;
    const int g    = lane >> 2, t2 = (lane & 3) * 2;
    const int lr   = tid >> 2, lc = (tid & 3) * 8;

    const int arow  = lane & 15;
    const int acol8 = (lane >> 4) << 3;
    const int brow  = ((lane >> 4) << 3) + (lane & 7);
    const int bcol8 = ((lane >> 3) & 1) << 3;

    float acc[4][4][4];
#pragma unroll
    for (int i = 0; i < 4; i++)
#pragma unroll
        for (int j = 0; j < 4; j++)
#pragma unroll
            for (int q = 0; q < 4; q++) acc[i][j][q] = 0.f;

    const __half* Ag = A  + (size_t)(bm + lr) * K + lc;
    const __half* Bg = Bt + (size_t)(bn + lr) * K + lc;
    const uint32_t aoff0 = (uint32_t)(lr * 40 + lc) * 2;
    const uint32_t aoff1 = (uint32_t)((lr + 64) * 40 + lc) * 2;
    const uint32_t bbase = (uint32_t)(128 * 40) * 2;

    auto issue = [&](int kt, int s) {
        const uint32_t sb = sbase + (uint32_t)s * STG_B;
        cpa16(sb + aoff0,         Ag + kt * BK);
        cpa16(sb + aoff1,         Ag + (size_t)64 * K + kt * BK);
        cpa16(sb + bbase + aoff0, Bg + kt * BK);
        cpa16(sb + bbase + aoff1, Bg + (size_t)64 * K + kt * BK);
        CP_COMMIT();
    };

    issue(0, 0); issue(1, 1); issue(2, 2);

    for (int kt = 0; kt < NT; kt++) {
        CP_WAIT(2);
        __syncthreads();
        if (kt + 3 < NT) issue(kt + 3, (kt + 3) & 3);

        const int s = kt & 3;
        __half* As = sm + (size_t)s * (2 * 128 * 40);
        __half* Bs = As + 128 * 40;
#pragma unroll
        for (int ks = 0; ks < BK; ks += 16) {
            unsigned af[4][4], bf[4][2];
#pragma unroll
            for (int mf = 0; mf < 4; mf++)
                ldsm4(af[mf], sptr(&As[(wm * 64 + mf * 16 + arow) * 40 + ks + acol8]));
#pragma unroll
            for (int np = 0; np < 2; np++) {
                unsigned t[4];
                ldsm4(t, sptr(&Bs[(wn * 32 + np * 16 + brow) * 40 + ks + bcol8]));
                bf[2*np][0]   = t[0]; bf[2*np][1]   = t[1];
                bf[2*np+1][0] = t[2]; bf[2*np+1][1] = t[3];
            }
#pragma unroll
            for (int mf = 0; mf < 4; mf++)
#pragma unroll
                for (int nf = 0; nf < 4; nf++)
                    mma16816(acc[mf][nf], af[mf], bf[nf]);
        }
    }

#pragma unroll
    for (int mf = 0; mf < 4; mf++) {
#pragma unroll
        for (int nf = 0; nf < 4; nf++) {
            const int m = bm + wm * 64 + mf * 16 + g;
            const int n = bn + wn * 32 + nf * 8 + t2;
            const float b0 = bias[n], b1 = bias[n + 1];
            const float v00 = acc[mf][nf][0] + b0, v01 = acc[mf][nf][1] + b1;
            const float v10 = acc[mf][nf][2] + b0, v11 = acc[mf][nf][3] + b1;
            if (EPI == 0) {
                float* C = (float*)Cout;
                *(float2*)&C[(size_t)m * N + n]       = make_float2(v00, v01);
                *(float2*)&C[(size_t)(m + 8) * N + n] = make_float2(v10, v11);
            } else { // EPI == 5: fused QKV
                const int b_ = m >> 11, s = m & (SEQ - 1);
                if (n < EMBD) {
                    const int h = n >> 6, d = n & 63;
                    *(__half2*)&g_q[(((size_t)(b_ * HEADS + h) * SEQ) + s) * HD + d] =
                        __floats2half2_rn(v00, v01);
                    *(__half2*)&g_q[(((size_t)(b_ * HEADS + h) * SEQ) + s + 8) * HD + d] =
                        __floats2half2_rn(v10, v11);
                } else if (n < EMBD + HD) {
                    const int d = n - EMBD;
                    *(__half2*)&g_k[((size_t)(b_ * SEQ) + s) * HD + d]     = __floats2half2_rn(v00, v01);
                    *(__half2*)&g_k[((size_t)(b_ * SEQ) + s + 8) * HD + d] = __floats2half2_rn(v10, v11);
                } else {
                    const int d = n - EMBD - HD;
                    g_vt[((size_t)(b_ * HD) + d)     * SEQ + s]     = __float2half(v00);
                    g_vt[((size_t)(b_ * HD) + d + 1) * SEQ + s]     = __float2half(v01);
                    g_vt[((size_t)(b_ * HD) + d)     * SEQ + s + 8] = __float2half(v10);
                    g_vt[((size_t)(b_ * HD) + d + 1) * SEQ + s + 8] = __float2half(v11);
                }
            }
        }
    }
}

// ---------------- flash attention: cp.async 2-stage K/V, registers-only S/P --------
// smem: Qs[128][72] + 2 x (Ks[64][72] + Vs[64][72])
#define ATTN_SMEM ((128*72 + 4*64*72) * 2)   // 55296 B

__global__ __launch_bounds__(256, 2)
void attn_kernel(const __half* __restrict__ Q, const __half* __restrict__ Kg,
                 const __half* __restrict__ Vt, __half* __restrict__ O)
{
    extern __shared__ __half sm[];
    __half* Qs = sm;                       // [128][72]
    const uint32_t sbase   = sptr(sm);
    const uint32_t kvbase  = sbase + 128 * 72 * 2;
    constexpr uint32_t KV_STG = 2 * 64 * 72 * 2;       // bytes per stage (K+V)
    constexpr uint32_t VOFF   = 64 * 72 * 2;

    const int tid  = threadIdx.x;
    const int bh   = blockIdx.y, b = bh >> 4, h = bh & 15, qt = blockIdx.x;
    const int warp = tid >> 5, lane = tid & 31;
    const int g    = lane >> 2, t2 = (lane & 3) * 2;

    const int brow  = ((lane >> 4) << 3) + (lane & 7);
    const int bcol8 = ((lane >> 3) & 1) << 3;

    {
        const __half* Qb = Q + ((size_t)bh * SEQ + qt * 128) * HD;
        const int lr = tid >> 1, lc = (tid & 1) * 32;
#pragma unroll
        for (int u = 0; u < 4; u++)
            *(uint4*)&Qs[lr * 72 + lc + u * 8] = *(const uint4*)&Qb[lr * HD + lc + u * 8];
    }

    const __half* Kb = Kg + (size_t)b * SEQ * HD;
    const __half* Vb = Vt + (size_t)b * HD * SEQ;
    const int r0c = tid >> 3,         cu0 = (tid & 7) * 8;
    const int r1c = (tid + 256) >> 3, cu1 = ((tid + 256) & 7) * 8;

    auto issue = [&](int kt, int s) {
        const uint32_t kb = kvbase + (uint32_t)s * KV_STG;
        cpa16(kb + (uint32_t)(r0c * 144 + cu0 * 2), Kb + ((size_t)kt * 64 + r0c) * HD + cu0);
        cpa16(kb + (uint32_t)(r1c * 144 + cu1 * 2), Kb + ((size_t)kt * 64 + r1c) * HD + cu1);
        cpa16(kb + VOFF + (uint32_t)(r0c * 144 + cu0 * 2), Vb + (size_t)r0c * SEQ + kt * 64 + cu0);
        cpa16(kb + VOFF + (uint32_t)(r1c * 144 + cu1 * 2), Vb + (size_t)r1c * SEQ + kt * 64 + cu1);
        CP_COMMIT();
    };
    issue(0, 0);

    __syncthreads();   // Qs visible
    unsigned qf[4][4];
    {
        const int arow  = lane & 15;
        const int acol8 = (lane >> 4) << 3;
#pragma unroll
        for (int kb = 0; kb < 4; kb++)
            ldsm4(qf[kb], sptr(&Qs[(warp * 16 + arow) * 72 + kb * 16 + acol8]));
    }

    float oacc[8][4];
#pragma unroll
    for (int nf = 0; nf < 8; nf++)
#pragma unroll
        for (int q = 0; q < 4; q++) oacc[nf][q] = 0.f;
    float m0 = -1e30f, m1 = -1e30f, l0 = 0.f, l1 = 0.f;
    const float scl = 0.125f;

    for (int kt = 0; kt < SEQ / 64; kt++) {
        CP_WAIT(0);
        __syncthreads();
        if (kt + 1 < SEQ / 64) issue(kt + 1, (kt + 1) & 1);

        __half* Ks = (__half*)(sm + 128 * 72) + (size_t)(kt & 1) * (2 * 64 * 72);
        __half* Vs = Ks + 64 * 72;

        // S = Q @ K^T
        float sacc[8][4];
#pragma unroll
        for (int nf = 0; nf < 8; nf++)
#pragma unroll
            for (int q = 0; q < 4; q++) sacc[nf][q] = 0.f;
#pragma unroll
        for (int kb = 0; kb < 4; kb++) {
            unsigned kf[4][4];
#pragma unroll
            for (int np = 0; np < 4; np++)
                ldsm4(kf[np], sptr(&Ks[(np * 16 + brow) * 72 + kb * 16 + bcol8]));
#pragma unroll
            for (int nf = 0; nf < 8; nf++) {
                const unsigned bfr[2] = { kf[nf >> 1][(nf & 1) * 2],
                                          kf[nf >> 1][(nf & 1) * 2 + 1] };
                mma16816(sacc[nf], qf[kb], bfr);
            }
        }

        // online softmax in registers
        float mx0 = -1e30f, mx1 = -1e30f;
#pragma unroll
        for (int nf = 0; nf < 8; nf++) {
#pragma unroll
            for (int q = 0; q < 4; q++) sacc[nf][q] *= scl;
            mx0 = fmaxf(mx0, fmaxf(sacc[nf][0], sacc[nf][1]));
            mx1 = fmaxf(mx1, fmaxf(sacc[nf][2], sacc[nf][3]));
        }
        mx0 = fmaxf(mx0, __shfl_xor_sync(0xffffffffu, mx0, 1));
        mx0 = fmaxf(mx0, __shfl_xor_sync(0xffffffffu, mx0, 2));
        mx1 = fmaxf(mx1, __shfl_xor_sync(0xffffffffu, mx1, 1));
        mx1 = fmaxf(mx1, __shfl_xor_sync(0xffffffffu, mx1, 2));
        const float mn0 = fmaxf(m0, mx0), mn1 = fmaxf(m1, mx1);

        unsigned ph[8][2];
        float ps0 = 0.f, ps1 = 0.f;
#pragma unroll
        for (int nf = 0; nf < 8; nf++) {
            const float p00 = __expf(sacc[nf][0] - mn0);
            const float p01 = __expf(sacc[nf][1] - mn0);
            const float p10 = __expf(sacc[nf][2] - mn1);
            const float p11 = __expf(sacc[nf][3] - mn1);
            ps0 += p00 + p01;
            ps1 += p10 + p11;
            ph[nf][0] = h2_as_u32(__floats2half2_rn(p00, p01));
            ph[nf][1] = h2_as_u32(__floats2half2_rn(p10, p11));
        }
        ps0 += __shfl_xor_sync(0xffffffffu, ps0, 1);
        ps0 += __shfl_xor_sync(0xffffffffu, ps0, 2);
        ps1 += __shfl_xor_sync(0xffffffffu, ps1, 1);
        ps1 += __shfl_xor_sync(0xffffffffu, ps1, 2);
        const float rs0 = __expf(m0 - mn0), rs1 = __expf(m1 - mn1);
        l0 = l0 * rs0 + ps0;  m0 = mn0;
        l1 = l1 * rs1 + ps1;  m1 = mn1;
#pragma unroll
        for (int nf = 0; nf < 8; nf++) {
            oacc[nf][0] *= rs0; oacc[nf][1] *= rs0;
            oacc[nf][2] *= rs1; oacc[nf][3] *= rs1;
        }

        // O += P @ V
#pragma unroll
        for (int kb = 0; kb < 4; kb++) {
            const unsigned af[4] = { ph[2*kb][0], ph[2*kb][1], ph[2*kb+1][0], ph[2*kb+1][1] };
            unsigned vf[4][4];
#pragma unroll
            for (int np = 0; np < 4; np++)
                ldsm4(vf[np], sptr(&Vs[(np * 16 + brow) * 72 + kb * 16 + bcol8]));
#pragma unroll
            for (int nd = 0; nd < 8; nd++) {
                const unsigned bfr[2] = { vf[nd >> 1][(nd & 1) * 2],
                                          vf[nd >> 1][(nd & 1) * 2 + 1] };
                mma16816(oacc[nd], af, bfr);
            }
        }
    }

    const float i0 = 1.f / l0, i1 = 1.f / l1;
    const int row = warp * 16 + g;
    const int s0 = qt * 128 + row;
#pragma unroll
    for (int nf = 0; nf < 8; nf++) {
        const int d = h * HD + nf * 8 + t2;
        *(__half2*)&O[((size_t)(b * SEQ) + s0) * EMBD + d] =
            __floats2half2_rn(oacc[nf][0] * i0, oacc[nf][1] * i0);
        *(__half2*)&O[((size_t)(b * SEQ) + s0 + 8) * EMBD + d] =
            __floats2half2_rn(oacc[nf][2] * i1, oacc[nf][3] * i1);
    }
}

// ---------------- launch ----------------
extern "C" void kernel_launch(void* const* d_in, const int* in_sizes, int n_in,
                              void* d_out, int out_size)
{
    const float* x  = (const float*)d_in[0];
    const float* Wq = (const float*)d_in[1];
    const float* bq = (const float*)d_in[2];
    const float* Wk = (const float*)d_in[3];
    const float* bk = (const float*)d_in[4];
    const float* Wv = (const float*)d_in[5];
    const float* bv = (const float*)d_in[6];
    const float* Wo = (const float*)d_in[7];
    const float* bo = (const float*)d_in[8];
    float* out = (float*)d_out;

    __half *xh, *wqkvt, *wot, *q, *k, *vt, *ao;
    float *bqkv;
    cudaGetSymbolAddress((void**)&xh,    g_xh);
    cudaGetSymbolAddress((void**)&wqkvt, g_wqkvt);
    cudaGetSymbolAddress((void**)&wot,   g_wot);
    cudaGetSymbolAddress((void**)&bqkv,  g_bqkv);
    cudaGetSymbolAddress((void**)&q,     g_q);
    cudaGetSymbolAddress((void**)&k,     g_k);
    cudaGetSymbolAddress((void**)&vt,    g_vt);
    cudaGetSymbolAddress((void**)&ao,    g_ao);

    cudaFuncSetAttribute(hgemm_kernel<5>, cudaFuncAttributeMaxDynamicSharedMemorySize, GEMM_SMEM);
    cudaFuncSetAttribute(hgemm_kernel<0>, cudaFuncAttributeMaxDynamicSharedMemorySize, GEMM_SMEM);
    cudaFuncSetAttribute(attn_kernel,     cudaFuncAttributeMaxDynamicSharedMemorySize, ATTN_SMEM);

    // prep (launches 0-4)
    f2h_kernel<<<(MROWS * EMBD / 4 + 255) / 256, 256>>>(x, xh, MROWS * EMBD / 4);
    tconv_kernel<<<dim3(EMBD / 32, EMBD / 32), dim3(32, 8)>>>(Wq, wqkvt, EMBD, EMBD);
    tconv2_kernel<<<dim3(HD / 32, EMBD / 32, 2), dim3(32, 8)>>>(Wk, Wv, wqkvt);
    tconv_kernel<<<dim3(EMBD / 32, EMBD / 32), dim3(32, 8)>>>(Wo, wot, EMBD, EMBD);
    bqkv_kernel<<<5, 256>>>(bq, bk, bv, bqkv);

    // fused QKV projection (launch 5 — ncu target)
    hgemm_kernel<5><<<dim3(NQKV / 128, MROWS / 128), 256, GEMM_SMEM>>>(xh, wqkvt, bqkv, nullptr, NQKV);

    // flash attention (launch 6)
    attn_kernel<<<dim3(SEQ / 128, BATCH * HEADS), 256, ATTN_SMEM>>>(q, k, vt, ao);

    // output projection -> fp32 d_out (launch 7)
    hgemm_kernel<0><<<dim3(EMBD / 128, MROWS / 128), 256, GEMM_SMEM>>>(ao, wot, bo, out, EMBD);
}